// round 8
// baseline (speedup 1.0000x reference)
#include <cuda_runtime.h>
#include <cuda_bf16.h>

#define BS 16
#define D 448
#define HW 4096
#define NELEM (BS * D * HW)

typedef unsigned int u32;

// ---- scratch ----
__device__ __nv_bfloat16 g_Vr_hi[NELEM], g_Vr_lo[NELEM];
__device__ __nv_bfloat16 g_Vs_hi[NELEM], g_Vs_lo[NELEM];
__device__ __nv_bfloat16 g_W_hi[3 * D * D], g_W_lo[3 * D * D];
__device__ __nv_bfloat16 g_Q_hi[NELEM], g_Q_lo[NELEM];
__device__ __nv_bfloat16 g_K_hi[NELEM], g_K_lo[NELEM];
__device__ __nv_bfloat16 g_V2_hi[NELEM], g_V2_lo[NELEM];
__device__ float g_scores[2 * BS * D * D];
__device__ __nv_bfloat16 g_al_hi[2 * BS * D * D], g_al_lo[2 * BS * D * D];
__device__ double g_Lsum;

__global__ void k_zero() { g_Lsum = 0.0; }

__device__ __forceinline__ u32 smem_u32(const void* p) {
    u32 a;
    asm("{ .reg .u64 t; cvta.to.shared.u64 t, %1; cvt.u32.u64 %0, t; }" : "=r"(a) : "l"(p));
    return a;
}

#define CP16(dst, src) \
    asm volatile("cp.async.cg.shared.global [%0], [%1], 16;" :: "r"(dst), "l"(src))
#define CP_COMMIT() asm volatile("cp.async.commit_group;" ::: "memory")
#define CP_WAIT(n)  asm volatile("cp.async.wait_group %0;" :: "n"(n) : "memory")

#define LDSM4(r0, r1, r2, r3, a)                                              \
    asm volatile("ldmatrix.sync.aligned.m8n8.x4.shared.b16 {%0,%1,%2,%3},[%4];" \
                 : "=r"(r0), "=r"(r1), "=r"(r2), "=r"(r3) : "r"(a))
#define LDSM4T(r0, r1, r2, r3, a)                                             \
    asm volatile("ldmatrix.sync.aligned.m8n8.x4.trans.shared.b16 {%0,%1,%2,%3},[%4];" \
                 : "=r"(r0), "=r"(r1), "=r"(r2), "=r"(r3) : "r"(a))
#define MMA(d, a0, a1, a2, a3, b0, b1)                                        \
    asm volatile(                                                             \
        "mma.sync.aligned.m16n8k16.row.col.f32.bf16.bf16.f32 "                \
        "{%0,%1,%2,%3},{%4,%5,%6,%7},{%8,%9},{%0,%1,%2,%3};"                  \
        : "+f"(d[0]), "+f"(d[1]), "+f"(d[2]), "+f"(d[3])                      \
        : "r"(a0), "r"(a1), "r"(a2), "r"(a3), "r"(b0), "r"(b1))

__device__ __forceinline__ void split2(float v, __nv_bfloat16& h, __nv_bfloat16& l) {
    h = __float2bfloat16(v);
    l = __float2bfloat16(v - __bfloat162float(h));
}
__device__ __forceinline__ u32 pack_bf(__nv_bfloat16 a, __nv_bfloat16 b) {
    return (u32)__bfloat16_as_ushort(a) | ((u32)__bfloat16_as_ushort(b) << 16);
}

__global__ void k_split_v(const float* __restrict__ Vr, const float* __restrict__ Vs) {
    int i = blockIdx.x * blockDim.x + threadIdx.x;
    int stride = gridDim.x * blockDim.x;
    for (; i < NELEM; i += stride) {
        __nv_bfloat16 h, l;
        split2(Vr[i], h, l); g_Vr_hi[i] = h; g_Vr_lo[i] = l;
        split2(Vs[i], h, l); g_Vs_hi[i] = h; g_Vs_lo[i] = l;
    }
}
__global__ void k_split_w(const float* __restrict__ Wq, const float* __restrict__ Wk,
                          const float* __restrict__ Wv) {
    int i = blockIdx.x * blockDim.x + threadIdx.x;
    if (i >= 3 * D * D) return;
    int w = i / (D * D), j = i % (D * D);
    const float* W = (w == 0) ? Wq : ((w == 1) ? Wk : Wv);
    __nv_bfloat16 h, l;
    split2(W[j], h, l);
    g_W_hi[i] = h; g_W_lo[i] = l;
}

// pitches (bytes)
#define PA 80     // A tiles: rows x 32 halves (64B) + 16B pad
#define PBT 144   // trans-B tiles: 32 rows x 64 halves (128B) + 16B pad

// =========================================================================
// k_scores: M=128(d) N=64(e) K=4096. cp.async double-buffered.
// =========================================================================
#define SCR_AH 0
#define SCR_AL 10240
#define SCR_BH 20480
#define SCR_BL 25600
#define SCR_BUFSZ 30720
#define SCR_SMEM (2 * SCR_BUFSZ)

__global__ __launch_bounds__(256, 2) void k_scores() {
    extern __shared__ char sm[];
    const u32 sb = smem_u32(sm);
    const int t = threadIdx.x, wid = t >> 5, l = t & 31;
    const int warp_m = wid & 3, warp_n = wid >> 2;

    const int z = blockIdx.z, b = z >> 1, neg = z & 1;
    const int bk = neg ? ((b + 1) & (BS - 1)) : b;
    const __nv_bfloat16* Ahi = g_Q_hi + (size_t)b * D * HW;
    const __nv_bfloat16* Alo = g_Q_lo + (size_t)b * D * HW;
    const __nv_bfloat16* Bhi = g_K_hi + (size_t)bk * D * HW;
    const __nv_bfloat16* Blo = g_K_lo + (size_t)bk * D * HW;
    float* C = g_scores + ((size_t)neg * BS + b) * D * D;

    const int m0 = blockIdx.y * 128, n0 = blockIdx.x * 64;

    // loader lane mapping (fixed per thread)
    const int la_m = t & 127, la_c = t >> 7;          // A: 2 iters (m, m) with c, c+2
    int la_gm = m0 + la_m; if (la_gm > 447) la_gm = 447;
    const int lb_n = t >> 2, lb_c = t & 3;            // B: 1 iter

    const u32 aRow = warp_m * 32 + (l & 15);
    const u32 aCol = (l >> 4) * 16;
    const u32 bRow = ((l >> 4) & 1) * 8 + (l & 7);
    const u32 bCol = ((l >> 3) & 1) * 16;

    float acc[2][4][4] = {};
    const int NC = HW / 32;

#define SCR_LOAD(i, buf) do {                                                     \
        const int k0_ = (i) * 32;                                                 \
        const u32 bo_ = sb + (buf) * SCR_BUFSZ;                                   \
        size_t gA = (size_t)la_gm * HW + k0_ + la_c * 8;                          \
        CP16(bo_ + SCR_AH + la_m * PA + la_c * 16, Ahi + gA);                     \
        CP16(bo_ + SCR_AL + la_m * PA + la_c * 16, Alo + gA);                     \
        size_t gA2 = gA + 16;                                                     \
        CP16(bo_ + SCR_AH + la_m * PA + la_c * 16 + 32, Ahi + gA2);               \
        CP16(bo_ + SCR_AL + la_m * PA + la_c * 16 + 32, Alo + gA2);               \
        size_t gB = (size_t)(n0 + lb_n) * HW + k0_ + lb_c * 8;                    \
        CP16(bo_ + SCR_BH + lb_n * PA + lb_c * 16, Bhi + gB);                     \
        CP16(bo_ + SCR_BL + lb_n * PA + lb_c * 16, Blo + gB);                     \
    } while (0)

    SCR_LOAD(0, 0);
    CP_COMMIT();

    for (int i = 0; i < NC; i++) {
        if (i + 1 < NC) {
            SCR_LOAD(i + 1, (i + 1) & 1);
            CP_COMMIT();
            CP_WAIT(1);
        } else {
            CP_WAIT(0);
        }
        __syncthreads();
        const u32 bo = sb + (i & 1) * SCR_BUFSZ;
#pragma unroll
        for (int k16 = 0; k16 < 2; k16++) {
            const u32 kb = k16 * 32;
            u32 ah[2][4], al[2][4];
#pragma unroll
            for (int ma = 0; ma < 2; ma++) {
                u32 off = (aRow + ma * 16) * PA + aCol + kb;
                LDSM4(ah[ma][0], ah[ma][1], ah[ma][2], ah[ma][3], bo + SCR_AH + off);
                LDSM4(al[ma][0], al[ma][1], al[ma][2], al[ma][3], bo + SCR_AL + off);
            }
            u32 bh[8], bl[8];
#pragma unroll
            for (int p = 0; p < 2; p++) {
                u32 off = (warp_n * 32 + p * 16 + bRow) * PA + bCol + kb;
                LDSM4(bh[p * 4 + 0], bh[p * 4 + 1], bh[p * 4 + 2], bh[p * 4 + 3], bo + SCR_BH + off);
                LDSM4(bl[p * 4 + 0], bl[p * 4 + 1], bl[p * 4 + 2], bl[p * 4 + 3], bo + SCR_BL + off);
            }
#pragma unroll
            for (int ma = 0; ma < 2; ma++)
#pragma unroll
                for (int na = 0; na < 4; na++) {
                    float* d = acc[ma][na];
                    u32 h0 = bh[na * 2], h1 = bh[na * 2 + 1];
                    u32 l0 = bl[na * 2], l1 = bl[na * 2 + 1];
                    MMA(d, ah[ma][0], ah[ma][1], ah[ma][2], ah[ma][3], h0, h1);
                    MMA(d, ah[ma][0], ah[ma][1], ah[ma][2], ah[ma][3], l0, l1);
                    MMA(d, al[ma][0], al[ma][1], al[ma][2], al[ma][3], h0, h1);
                }
        }
        __syncthreads();
    }

    const float inv_coef = 0.047245559f;
    const int r = l >> 2, c2 = (l & 3) * 2;
#pragma unroll
    for (int ma = 0; ma < 2; ma++)
#pragma unroll
        for (int na = 0; na < 4; na++)
#pragma unroll
            for (int rr = 0; rr < 2; rr++) {
                int gm = m0 + warp_m * 32 + ma * 16 + rr * 8 + r;
                if (gm < 448) {
                    int gn = n0 + warp_n * 32 + na * 8 + c2;
                    float2 o = make_float2(acc[ma][na][rr * 2] * inv_coef,
                                           acc[ma][na][rr * 2 + 1] * inv_coef);
                    *(float2*)(C + (size_t)gm * D + gn) = o;
                }
            }
}

// =========================================================================
// k_proj: M=128(d) N=64(h) K=448. cp.async double-buffered, trans-B.
// =========================================================================
#define PRJ_AH 0
#define PRJ_AL 10240
#define PRJ_BH 20480
#define PRJ_BL 25088
#define PRJ_BUFSZ 29696
#define PRJ_SMEM (2 * PRJ_BUFSZ)

__global__ __launch_bounds__(256, 2) void k_proj() {
    extern __shared__ char sm[];
    const u32 sb = smem_u32(sm);
    const int t = threadIdx.x, wid = t >> 5, l = t & 31;
    const int warp_m = wid & 3, warp_n = wid >> 2;

    const int z = blockIdx.z, b = z / 3, w = z % 3;
    const __nv_bfloat16* Ahi = g_W_hi + w * D * D;
    const __nv_bfloat16* Alo = g_W_lo + w * D * D;
    const __nv_bfloat16* Bhi = ((w == 0) ? g_Vs_hi : g_Vr_hi) + (size_t)b * D * HW;
    const __nv_bfloat16* Blo = ((w == 0) ? g_Vs_lo : g_Vr_lo) + (size_t)b * D * HW;
    __nv_bfloat16* Chi = ((w == 0) ? g_Q_hi : ((w == 1) ? g_K_hi : g_V2_hi)) + (size_t)b * D * HW;
    __nv_bfloat16* Clo = ((w == 0) ? g_Q_lo : ((w == 1) ? g_K_lo : g_V2_lo)) + (size_t)b * D * HW;

    const int m0 = blockIdx.y * 128, n0 = blockIdx.x * 64;

    const int la_m = t & 127, la_c = t >> 7;
    int la_gm = m0 + la_m; if (la_gm > 447) la_gm = 447;
    const int lb_r = t >> 3, lb_c = t & 7;

    const u32 aRow = warp_m * 32 + (l & 15);
    const u32 aCol = (l >> 4) * 16;
    const u32 btRow = (l & 15);
    const u32 btCol = (l >> 4) * 16;

    float acc[2][4][4] = {};
    const int NC = D / 32;

#define PRJ_LOAD(i, buf) do {                                                     \
        const int k0_ = (i) * 32;                                                 \
        const u32 bo_ = sb + (buf) * PRJ_BUFSZ;                                   \
        size_t gA = (size_t)la_gm * D + k0_ + la_c * 8;                           \
        CP16(bo_ + PRJ_AH + la_m * PA + la_c * 16, Ahi + gA);                     \
        CP16(bo_ + PRJ_AL + la_m * PA + la_c * 16, Alo + gA);                     \
        size_t gA2 = gA + 16;                                                     \
        CP16(bo_ + PRJ_AH + la_m * PA + la_c * 16 + 32, Ahi + gA2);               \
        CP16(bo_ + PRJ_AL + la_m * PA + la_c * 16 + 32, Alo + gA2);               \
        size_t gB = (size_t)(k0_ + lb_r) * HW + n0 + lb_c * 8;                    \
        CP16(bo_ + PRJ_BH + lb_r * PBT + lb_c * 16, Bhi + gB);                    \
        CP16(bo_ + PRJ_BL + lb_r * PBT + lb_c * 16, Blo + gB);                    \
    } while (0)

    PRJ_LOAD(0, 0);
    CP_COMMIT();

    for (int i = 0; i < NC; i++) {
        if (i + 1 < NC) {
            PRJ_LOAD(i + 1, (i + 1) & 1);
            CP_COMMIT();
            CP_WAIT(1);
        } else {
            CP_WAIT(0);
        }
        __syncthreads();
        const u32 bo = sb + (i & 1) * PRJ_BUFSZ;
#pragma unroll
        for (int k16 = 0; k16 < 2; k16++) {
            u32 ah[2][4], al[2][4];
#pragma unroll
            for (int ma = 0; ma < 2; ma++) {
                u32 off = (aRow + ma * 16) * PA + aCol + k16 * 32;
                LDSM4(ah[ma][0], ah[ma][1], ah[ma][2], ah[ma][3], bo + PRJ_AH + off);
                LDSM4(al[ma][0], al[ma][1], al[ma][2], al[ma][3], bo + PRJ_AL + off);
            }
            u32 bh[8], bl[8];
#pragma unroll
            for (int p = 0; p < 2; p++) {
                u32 off = (k16 * 16 + btRow) * PBT + (warp_n * 32 + p * 16) * 2 + btCol;
                LDSM4T(bh[p * 4 + 0], bh[p * 4 + 1], bh[p * 4 + 2], bh[p * 4 + 3], bo + PRJ_BH + off);
                LDSM4T(bl[p * 4 + 0], bl[p * 4 + 1], bl[p * 4 + 2], bl[p * 4 + 3], bo + PRJ_BL + off);
            }
#pragma unroll
            for (int ma = 0; ma < 2; ma++)
#pragma unroll
                for (int na = 0; na < 4; na++) {
                    float* d = acc[ma][na];
                    u32 h0 = bh[na * 2], h1 = bh[na * 2 + 1];
                    u32 l0 = bl[na * 2], l1 = bl[na * 2 + 1];
                    MMA(d, ah[ma][0], ah[ma][1], ah[ma][2], ah[ma][3], h0, h1);
                    MMA(d, ah[ma][0], ah[ma][1], ah[ma][2], ah[ma][3], l0, l1);
                    MMA(d, al[ma][0], al[ma][1], al[ma][2], al[ma][3], h0, h1);
                }
        }
        __syncthreads();
    }

    const int r = l >> 2, c2 = (l & 3) * 2;
#pragma unroll
    for (int ma = 0; ma < 2; ma++)
#pragma unroll
        for (int na = 0; na < 4; na++)
#pragma unroll
            for (int rr = 0; rr < 2; rr++) {
                int gm = m0 + warp_m * 32 + ma * 16 + rr * 8 + r;
                if (gm < 448) {
                    int gn = n0 + warp_n * 32 + na * 8 + c2;
                    float v0 = acc[ma][na][rr * 2], v1 = acc[ma][na][rr * 2 + 1];
                    __nv_bfloat16 h0, l0_, h1, l1_;
                    split2(v0, h0, l0_);
                    split2(v1, h1, l1_);
                    size_t g = (size_t)gm * HW + gn;
                    *(u32*)(Chi + g) = pack_bf(h0, h1);
                    *(u32*)(Clo + g) = pack_bf(l0_, l1_);
                }
            }
}

// ---------------- softmax + split alpha ----------------
__global__ void k_softmax() {
    const int warp = (blockIdx.x * blockDim.x + threadIdx.x) >> 5;
    const int lane = threadIdx.x & 31;
    if (warp >= 2 * BS * D) return;
    const float* row = g_scores + (size_t)warp * D;
    __nv_bfloat16* oh = g_al_hi + (size_t)warp * D;
    __nv_bfloat16* ol = g_al_lo + (size_t)warp * D;

    float m = -1e30f;
    for (int i = lane; i < D; i += 32) m = fmaxf(m, row[i]);
#pragma unroll
    for (int off = 16; off > 0; off >>= 1) m = fmaxf(m, __shfl_xor_sync(0xffffffffu, m, off));
    float s = 0.f;
    float e[14];
#pragma unroll
    for (int j = 0; j < 14; j++) { e[j] = __expf(row[lane + 32 * j] - m); s += e[j]; }
#pragma unroll
    for (int off = 16; off > 0; off >>= 1) s += __shfl_xor_sync(0xffffffffu, s, off);
    float inv = 1.0f / s;
#pragma unroll
    for (int j = 0; j < 14; j++) {
        __nv_bfloat16 h, l;
        split2(e[j] * inv, h, l);
        oh[lane + 32 * j] = h;
        ol[lane + 32 * j] = l;
    }
}

// =========================================================================
// k_out: M=128(d) N=64(h) K=448. Dual A (pos/neg), cp.async double-buffered.
// =========================================================================
#define OUT_P_H 0
#define OUT_P_L 10240
#define OUT_N_H 20480
#define OUT_N_L 30720
#define OUT_BH 40960
#define OUT_BL 45568
#define OUT_BUFSZ 50176
#define OUT_SMEM (2 * OUT_BUFSZ)

__global__ __launch_bounds__(256) void k_out(const float* __restrict__ Vs,
                                             float* __restrict__ out) {
    extern __shared__ char sm[];
    const u32 sb = smem_u32(sm);
    const int t = threadIdx.x, wid = t >> 5, l = t & 31;
    const int warp_m = wid & 3, warp_n = wid >> 2;

    const int b = blockIdx.z;
    const __nv_bfloat16* A1h = g_al_hi + (size_t)b * D * D;
    const __nv_bfloat16* A1l = g_al_lo + (size_t)b * D * D;
    const __nv_bfloat16* A2h = g_al_hi + (size_t)(BS + b) * D * D;
    const __nv_bfloat16* A2l = g_al_lo + (size_t)(BS + b) * D * D;
    const __nv_bfloat16* Bhi = g_V2_hi + (size_t)b * D * HW;
    const __nv_bfloat16* Blo = g_V2_lo + (size_t)b * D * HW;

    const int m0 = blockIdx.y * 128, n0 = blockIdx.x * 64;

    const int la_m = t & 127, la_c = t >> 7;
    int la_gm = m0 + la_m; if (la_gm > 447) la_gm = 447;
    const int lb_r = t >> 3, lb_c = t & 7;

    const u32 aRow = warp_m * 32 + (l & 15);
    const u32 aCol = (l >> 4) * 16;
    const u32 btRow = (l & 15);
    const u32 btCol = (l >> 4) * 16;

    float accP[2][4][4] = {};
    float accN[2][4][4] = {};
    const int NC = D / 32;

#define OUT_LOAD(i, buf) do {                                                     \
        const int k0_ = (i) * 32;                                                 \
        const u32 bo_ = sb + (buf) * OUT_BUFSZ;                                   \
        size_t gA = (size_t)la_gm * D + k0_ + la_c * 8;                           \
        u32 sAoff = la_m * PA + la_c * 16;                                        \
        CP16(bo_ + OUT_P_H + sAoff, A1h + gA);                                    \
        CP16(bo_ + OUT_P_L + sAoff, A1l + gA);                                    \
        CP16(bo_ + OUT_N_H + sAoff, A2h + gA);                                    \
        CP16(bo_ + OUT_N_L + sAoff, A2l + gA);                                    \
        size_t gA2 = gA + 16;                                                     \
        CP16(bo_ + OUT_P_H + sAoff + 32, A1h + gA2);                              \
        CP16(bo_ + OUT_P_L + sAoff + 32, A1l + gA2);                              \
        CP16(bo_ + OUT_N_H + sAoff + 32, A2h + gA2);                              \
        CP16(bo_ + OUT_N_L + sAoff + 32, A2l + gA2);                              \
        size_t gB = (size_t)(k0_ + lb_r) * HW + n0 + lb_c * 8;                    \
        CP16(bo_ + OUT_BH + lb_r * PBT + lb_c * 16, Bhi + gB);                    \
        CP16(bo_ + OUT_BL + lb_r * PBT + lb_c * 16, Blo + gB);                    \
    } while (0)

    OUT_LOAD(0, 0);
    CP_COMMIT();

    for (int i = 0; i < NC; i++) {
        if (i + 1 < NC) {
            OUT_LOAD(i + 1, (i + 1) & 1);
            CP_COMMIT();
            CP_WAIT(1);
        } else {
            CP_WAIT(0);
        }
        __syncthreads();
        const u32 bo = sb + (i & 1) * OUT_BUFSZ;
#pragma unroll
        for (int k16 = 0; k16 < 2; k16++) {
            u32 bh[8], bl[8];
#pragma unroll
            for (int p = 0; p < 2; p++) {
                u32 off = (k16 * 16 + btRow) * PBT + (warp_n * 32 + p * 16) * 2 + btCol;
                LDSM4T(bh[p * 4 + 0], bh[p * 4 + 1], bh[p * 4 + 2], bh[p * 4 + 3], bo + OUT_BH + off);
                LDSM4T(bl[p * 4 + 0], bl[p * 4 + 1], bl[p * 4 + 2], bl[p * 4 + 3], bo + OUT_BL + off);
            }
#pragma unroll
            for (int ma = 0; ma < 2; ma++) {
                u32 off = (aRow + ma * 16) * PA + aCol + k16 * 32;
                u32 ph[4], pl[4], nh[4], nl[4];
                LDSM4(ph[0], ph[1], ph[2], ph[3], bo + OUT_P_H + off);
                LDSM4(pl[0], pl[1], pl[2], pl[3], bo + OUT_P_L + off);
                LDSM4(nh[0], nh[1], nh[2], nh[3], bo + OUT_N_H + off);
                LDSM4(nl[0], nl[1], nl[2], nl[3], bo + OUT_N_L + off);
#pragma unroll
                for (int na = 0; na < 4; na++) {
                    u32 h0 = bh[na * 2], h1 = bh[na * 2 + 1];
                    u32 l0 = bl[na * 2], l1 = bl[na * 2 + 1];
                    float* dp = accP[ma][na];
                    float* dn = accN[ma][na];
                    MMA(dp, ph[0], ph[1], ph[2], ph[3], h0, h1);
                    MMA(dp, ph[0], ph[1], ph[2], ph[3], l0, l1);
                    MMA(dp, pl[0], pl[1], pl[2], pl[3], h0, h1);
                    MMA(dn, nh[0], nh[1], nh[2], nh[3], h0, h1);
                    MMA(dn, nh[0], nh[1], nh[2], nh[3], l0, l1);
                    MMA(dn, nl[0], nl[1], nl[2], nl[3], h0, h1);
                }
            }
        }
        __syncthreads();
    }

    float lsum = 0.f;
    const int r = l >> 2, c2 = (l & 3) * 2;
#pragma unroll
    for (int ma = 0; ma < 2; ma++)
#pragma unroll
        for (int na = 0; na < 4; na++)
#pragma unroll
            for (int rr = 0; rr < 2; rr++) {
                int gm = m0 + warp_m * 32 + ma * 16 + rr * 8 + r;
                if (gm < 448) {
                    int gn = n0 + warp_n * 32 + na * 8 + c2;
                    float p0 = accP[ma][na][rr * 2], p1 = accP[ma][na][rr * 2 + 1];
                    float q0 = accN[ma][na][rr * 2], q1 = accN[ma][na][rr * 2 + 1];
                    size_t g = ((size_t)b * D + gm) * HW + gn;
                    float2 vs = *(const float2*)(Vs + g);
                    *(float2*)(out + g) = make_float2(vs.x + p0, vs.y + p1);
                    lsum += fmaxf(q0 - p0 + 12.0f, 0.0f);
                    lsum += fmaxf(q1 - p1 + 12.0f, 0.0f);
                }
            }

    __syncthreads();
    float* red = (float*)sm;
    red[t] = lsum;
    __syncthreads();
#pragma unroll
    for (int s = 128; s > 0; s >>= 1) {
        if (t < s) red[t] += red[t + s];
        __syncthreads();
    }
    if (t == 0) atomicAdd(&g_Lsum, (double)red[0]);
}

__global__ void k_final(float* out, int out_size) {
    if (out_size > NELEM)
        out[NELEM] = (float)(g_Lsum / (double)NELEM);
}

extern "C" void kernel_launch(void* const* d_in, const int* in_sizes, int n_in,
                              void* d_out, int out_size) {
    const float* Vr = (const float*)d_in[0];
    const float* Vs = (const float*)d_in[1];
    const float* Wq = (const float*)d_in[2];
    const float* Wk = (const float*)d_in[3];
    const float* Wv = (const float*)d_in[4];
    float* out = (float*)d_out;

    cudaFuncSetAttribute(k_proj, cudaFuncAttributeMaxDynamicSharedMemorySize, PRJ_SMEM);
    cudaFuncSetAttribute(k_scores, cudaFuncAttributeMaxDynamicSharedMemorySize, SCR_SMEM);
    cudaFuncSetAttribute(k_out, cudaFuncAttributeMaxDynamicSharedMemorySize, OUT_SMEM);

    k_zero<<<1, 1>>>();
    k_split_v<<<14336, 256>>>(Vr, Vs);
    k_split_w<<<(3 * D * D + 255) / 256, 256>>>(Wq, Wk, Wv);
    k_proj<<<dim3(HW / 64, 4, BS * 3), 256, PRJ_SMEM>>>();
    k_scores<<<dim3(D / 64, 4, BS * 2), 256, SCR_SMEM>>>();
    k_softmax<<<(2 * BS * D * 32 + 255) / 256, 256>>>();
    k_out<<<dim3(HW / 64, 4, BS), 256, OUT_SMEM>>>(Vs, out);
    k_final<<<1, 1>>>(out, out_size);
}

// round 9
// speedup vs baseline: 1.4208x; 1.4208x over previous
#include <cuda_runtime.h>
#include <cuda_bf16.h>

#define BS 16
#define D 448
#define HW 4096
#define NELEM (BS * D * HW)

typedef unsigned int u32;

// ---- scratch ----
__device__ __nv_bfloat16 g_Vr_hi[NELEM], g_Vr_lo[NELEM];
__device__ __nv_bfloat16 g_Vs_hi[NELEM], g_Vs_lo[NELEM];
__device__ __nv_bfloat16 g_W_hi[3 * D * D], g_W_lo[3 * D * D];
__device__ __nv_bfloat16 g_Q_hi[NELEM], g_Q_lo[NELEM];
__device__ __nv_bfloat16 g_K_hi[NELEM], g_K_lo[NELEM];
__device__ __nv_bfloat16 g_V2_hi[NELEM], g_V2_lo[NELEM];
__device__ float g_scores[2 * BS * D * D];
__device__ __nv_bfloat16 g_al_hi[2 * BS * D * D], g_al_lo[2 * BS * D * D];
__device__ double g_Lsum;

__global__ void k_zero() { g_Lsum = 0.0; }

__device__ __forceinline__ u32 smem_u32(const void* p) {
    u32 a;
    asm("{ .reg .u64 t; cvta.to.shared.u64 t, %1; cvt.u32.u64 %0, t; }" : "=r"(a) : "l"(p));
    return a;
}

#define LDSM4(r0, r1, r2, r3, a)                                              \
    asm volatile("ldmatrix.sync.aligned.m8n8.x4.shared.b16 {%0,%1,%2,%3},[%4];" \
                 : "=r"(r0), "=r"(r1), "=r"(r2), "=r"(r3) : "r"(a))
#define LDSM4T(r0, r1, r2, r3, a)                                             \
    asm volatile("ldmatrix.sync.aligned.m8n8.x4.trans.shared.b16 {%0,%1,%2,%3},[%4];" \
                 : "=r"(r0), "=r"(r1), "=r"(r2), "=r"(r3) : "r"(a))
#define MMA(d, a0, a1, a2, a3, b0, b1)                                        \
    asm volatile(                                                             \
        "mma.sync.aligned.m16n8k16.row.col.f32.bf16.bf16.f32 "                \
        "{%0,%1,%2,%3},{%4,%5,%6,%7},{%8,%9},{%0,%1,%2,%3};"                  \
        : "+f"(d[0]), "+f"(d[1]), "+f"(d[2]), "+f"(d[3])                      \
        : "r"(a0), "r"(a1), "r"(a2), "r"(a3), "r"(b0), "r"(b1))

__device__ __forceinline__ void split2(float v, __nv_bfloat16& h, __nv_bfloat16& l) {
    h = __float2bfloat16(v);
    l = __float2bfloat16(v - __bfloat162float(h));
}
__device__ __forceinline__ u32 pack_bf(__nv_bfloat16 a, __nv_bfloat16 b) {
    return (u32)__bfloat16_as_ushort(a) | ((u32)__bfloat16_as_ushort(b) << 16);
}

__global__ void k_split_v(const float* __restrict__ Vr, const float* __restrict__ Vs) {
    int i = blockIdx.x * blockDim.x + threadIdx.x;
    int stride = gridDim.x * blockDim.x;
    for (; i < NELEM; i += stride) {
        __nv_bfloat16 h, l;
        split2(Vr[i], h, l); g_Vr_hi[i] = h; g_Vr_lo[i] = l;
        split2(Vs[i], h, l); g_Vs_hi[i] = h; g_Vs_lo[i] = l;
    }
}
__global__ void k_split_w(const float* __restrict__ Wq, const float* __restrict__ Wk,
                          const float* __restrict__ Wv) {
    int i = blockIdx.x * blockDim.x + threadIdx.x;
    if (i >= 3 * D * D) return;
    int w = i / (D * D), j = i % (D * D);
    const float* W = (w == 0) ? Wq : ((w == 1) ? Wk : Wv);
    __nv_bfloat16 h, l;
    split2(W[j], h, l);
    g_W_hi[i] = h; g_W_lo[i] = l;
}

// pitches (bytes)
#define PA 80     // A/K-major tiles: rows x 32 halves (64B) + 16B pad
#define PBT 144   // trans-B 64-wide: 32 rows x 64 halves (128B) + 16B pad
#define PBT2 272  // trans-B 128-wide: 32 rows x 128 halves (256B) + 16B pad

// =========================================================================
// k_scores (pos+neg fused): M=128(d) N=64(e) K=4096.
// A=Q[b] shared; B_p=K[b], B_n=K[b+1]. Dual accumulators.
// =========================================================================
#define SCR_AH 0
#define SCR_AL 10240
#define SCR_PH 20480
#define SCR_PL 25600
#define SCR_NH 30720
#define SCR_NL 35840
#define SCR_SMEM 40960

__global__ __launch_bounds__(256, 2) void k_scores() {
    extern __shared__ char sm[];
    const u32 sb = smem_u32(sm);
    const int t = threadIdx.x, wid = t >> 5, l = t & 31;
    const int warp_m = wid & 3, warp_n = wid >> 2;

    const int b = blockIdx.z;
    const int bk = (b + 1) & (BS - 1);
    const __nv_bfloat16* Ahi = g_Q_hi + (size_t)b * D * HW;
    const __nv_bfloat16* Alo = g_Q_lo + (size_t)b * D * HW;
    const __nv_bfloat16* Phi = g_K_hi + (size_t)b * D * HW;
    const __nv_bfloat16* Plo = g_K_lo + (size_t)b * D * HW;
    const __nv_bfloat16* Nhi = g_K_hi + (size_t)bk * D * HW;
    const __nv_bfloat16* Nlo = g_K_lo + (size_t)bk * D * HW;
    float* Cp = g_scores + (size_t)b * D * D;
    float* Cn = g_scores + (size_t)(BS + b) * D * D;

    const int m0 = blockIdx.y * 128, n0 = blockIdx.x * 64;

    const int la_m = t & 127, la_c = t >> 7;
    int la_gm = m0 + la_m; if (la_gm > 447) la_gm = 447;
    const int lb_n = t >> 2, lb_c = t & 3;

    const u32 aRow = warp_m * 32 + (l & 15);
    const u32 aCol = (l >> 4) * 16;
    const u32 bRow = ((l >> 4) & 1) * 8 + (l & 7);
    const u32 bCol = ((l >> 3) & 1) * 16;

    float accP[2][4][4] = {};
    float accN[2][4][4] = {};

    for (int k0 = 0; k0 < HW; k0 += 32) {
#pragma unroll
        for (int i = 0; i < 2; i++) {
            int c = la_c + 2 * i;
            const size_t g = (size_t)la_gm * HW + k0 + c * 8;
            *(uint4*)(sm + SCR_AH + la_m * PA + c * 16) = *(const uint4*)(Ahi + g);
            *(uint4*)(sm + SCR_AL + la_m * PA + c * 16) = *(const uint4*)(Alo + g);
        }
        {
            const size_t g = (size_t)(n0 + lb_n) * HW + k0 + lb_c * 8;
            const u32 so = lb_n * PA + lb_c * 16;
            *(uint4*)(sm + SCR_PH + so) = *(const uint4*)(Phi + g);
            *(uint4*)(sm + SCR_PL + so) = *(const uint4*)(Plo + g);
            *(uint4*)(sm + SCR_NH + so) = *(const uint4*)(Nhi + g);
            *(uint4*)(sm + SCR_NL + so) = *(const uint4*)(Nlo + g);
        }
        __syncthreads();
#pragma unroll
        for (int k16 = 0; k16 < 2; k16++) {
            const u32 kb = k16 * 32;
            u32 ph[8], pl[8], nh[8], nl[8];
#pragma unroll
            for (int p = 0; p < 2; p++) {
                u32 off = (warp_n * 32 + p * 16 + bRow) * PA + bCol + kb;
                LDSM4(ph[p * 4 + 0], ph[p * 4 + 1], ph[p * 4 + 2], ph[p * 4 + 3], sb + SCR_PH + off);
                LDSM4(pl[p * 4 + 0], pl[p * 4 + 1], pl[p * 4 + 2], pl[p * 4 + 3], sb + SCR_PL + off);
                LDSM4(nh[p * 4 + 0], nh[p * 4 + 1], nh[p * 4 + 2], nh[p * 4 + 3], sb + SCR_NH + off);
                LDSM4(nl[p * 4 + 0], nl[p * 4 + 1], nl[p * 4 + 2], nl[p * 4 + 3], sb + SCR_NL + off);
            }
#pragma unroll
            for (int ma = 0; ma < 2; ma++) {
                u32 aoff = (aRow + ma * 16) * PA + aCol + kb;
                u32 a4[4];
                LDSM4(a4[0], a4[1], a4[2], a4[3], sb + SCR_AH + aoff);
#pragma unroll
                for (int na = 0; na < 4; na++) {
                    MMA(accP[ma][na], a4[0], a4[1], a4[2], a4[3], ph[na * 2], ph[na * 2 + 1]);
                    MMA(accP[ma][na], a4[0], a4[1], a4[2], a4[3], pl[na * 2], pl[na * 2 + 1]);
                    MMA(accN[ma][na], a4[0], a4[1], a4[2], a4[3], nh[na * 2], nh[na * 2 + 1]);
                    MMA(accN[ma][na], a4[0], a4[1], a4[2], a4[3], nl[na * 2], nl[na * 2 + 1]);
                }
                LDSM4(a4[0], a4[1], a4[2], a4[3], sb + SCR_AL + aoff);
#pragma unroll
                for (int na = 0; na < 4; na++) {
                    MMA(accP[ma][na], a4[0], a4[1], a4[2], a4[3], ph[na * 2], ph[na * 2 + 1]);
                    MMA(accN[ma][na], a4[0], a4[1], a4[2], a4[3], nh[na * 2], nh[na * 2 + 1]);
                }
            }
        }
        __syncthreads();
    }

    const float inv_coef = 0.047245559f;
    const int r = l >> 2, c2 = (l & 3) * 2;
#pragma unroll
    for (int ma = 0; ma < 2; ma++)
#pragma unroll
        for (int na = 0; na < 4; na++)
#pragma unroll
            for (int rr = 0; rr < 2; rr++) {
                int gm = m0 + warp_m * 32 + ma * 16 + rr * 8 + r;
                if (gm < 448) {
                    int gn = n0 + warp_n * 32 + na * 8 + c2;
                    float2 op = make_float2(accP[ma][na][rr * 2] * inv_coef,
                                            accP[ma][na][rr * 2 + 1] * inv_coef);
                    float2 on = make_float2(accN[ma][na][rr * 2] * inv_coef,
                                            accN[ma][na][rr * 2 + 1] * inv_coef);
                    *(float2*)(Cp + (size_t)gm * D + gn) = op;
                    *(float2*)(Cn + (size_t)gm * D + gn) = on;
                }
            }
}

// =========================================================================
// k_proj: M=128(d) N=128(h) K=448. Warp tile 32x64, A-frags streamed.
// =========================================================================
#define PRJ_AH 0
#define PRJ_AL 10240
#define PRJ_BH 20480
#define PRJ_BL 29184
#define PRJ_SMEM 37888

__global__ __launch_bounds__(256, 2) void k_proj() {
    extern __shared__ char sm[];
    const u32 sb = smem_u32(sm);
    const int t = threadIdx.x, wid = t >> 5, l = t & 31;
    const int warp_m = wid & 3, warp_n = wid >> 2;

    const int z = blockIdx.z, b = z / 3, w = z % 3;
    const __nv_bfloat16* Ahi = g_W_hi + w * D * D;
    const __nv_bfloat16* Alo = g_W_lo + w * D * D;
    const __nv_bfloat16* Bhi = ((w == 0) ? g_Vs_hi : g_Vr_hi) + (size_t)b * D * HW;
    const __nv_bfloat16* Blo = ((w == 0) ? g_Vs_lo : g_Vr_lo) + (size_t)b * D * HW;
    __nv_bfloat16* Chi = ((w == 0) ? g_Q_hi : ((w == 1) ? g_K_hi : g_V2_hi)) + (size_t)b * D * HW;
    __nv_bfloat16* Clo = ((w == 0) ? g_Q_lo : ((w == 1) ? g_K_lo : g_V2_lo)) + (size_t)b * D * HW;

    const int m0 = blockIdx.y * 128, n0 = blockIdx.x * 128;

    const int la_m = t & 127, la_c = t >> 7;
    int la_gm = m0 + la_m; if (la_gm > 447) la_gm = 447;
    const int lb_r = t >> 4, lb_c = t & 15;   // B: 32 rows x 16 uint4; 2 iters

    const u32 aRow = warp_m * 32 + (l & 15);
    const u32 aCol = (l >> 4) * 16;
    const u32 btRow = (l & 15);
    const u32 btCol = (l >> 4) * 16;

    float acc[2][8][4] = {};

    for (int k0 = 0; k0 < D; k0 += 32) {
#pragma unroll
        for (int i = 0; i < 2; i++) {
            int c = la_c + 2 * i;
            const size_t g = (size_t)la_gm * D + k0 + c * 8;
            *(uint4*)(sm + PRJ_AH + la_m * PA + c * 16) = *(const uint4*)(Ahi + g);
            *(uint4*)(sm + PRJ_AL + la_m * PA + c * 16) = *(const uint4*)(Alo + g);
        }
#pragma unroll
        for (int i = 0; i < 2; i++) {
            int idx = t + 256 * i;
            int r = idx >> 4, c = idx & 15;
            const size_t g = (size_t)(k0 + r) * HW + n0 + c * 8;
            *(uint4*)(sm + PRJ_BH + r * PBT2 + c * 16) = *(const uint4*)(Bhi + g);
            *(uint4*)(sm + PRJ_BL + r * PBT2 + c * 16) = *(const uint4*)(Blo + g);
        }
        __syncthreads();
#pragma unroll
        for (int k16 = 0; k16 < 2; k16++) {
            u32 bh[16], bl[16];
#pragma unroll
            for (int p = 0; p < 4; p++) {
                u32 off = (k16 * 16 + btRow) * PBT2 + (warp_n * 64 + p * 16) * 2 + btCol;
                LDSM4T(bh[p * 4 + 0], bh[p * 4 + 1], bh[p * 4 + 2], bh[p * 4 + 3], sb + PRJ_BH + off);
                LDSM4T(bl[p * 4 + 0], bl[p * 4 + 1], bl[p * 4 + 2], bl[p * 4 + 3], sb + PRJ_BL + off);
            }
#pragma unroll
            for (int ma = 0; ma < 2; ma++) {
                u32 aoff = (aRow + ma * 16) * PA + aCol + k16 * 32;
                u32 a4[4];
                LDSM4(a4[0], a4[1], a4[2], a4[3], sb + PRJ_AH + aoff);
#pragma unroll
                for (int na = 0; na < 8; na++) {
                    MMA(acc[ma][na], a4[0], a4[1], a4[2], a4[3], bh[na * 2], bh[na * 2 + 1]);
                    MMA(acc[ma][na], a4[0], a4[1], a4[2], a4[3], bl[na * 2], bl[na * 2 + 1]);
                }
                LDSM4(a4[0], a4[1], a4[2], a4[3], sb + PRJ_AL + aoff);
#pragma unroll
                for (int na = 0; na < 8; na++)
                    MMA(acc[ma][na], a4[0], a4[1], a4[2], a4[3], bh[na * 2], bh[na * 2 + 1]);
            }
        }
        __syncthreads();
    }

    const int r = l >> 2, c2 = (l & 3) * 2;
#pragma unroll
    for (int ma = 0; ma < 2; ma++)
#pragma unroll
        for (int na = 0; na < 8; na++)
#pragma unroll
            for (int rr = 0; rr < 2; rr++) {
                int gm = m0 + warp_m * 32 + ma * 16 + rr * 8 + r;
                if (gm < 448) {
                    int gn = n0 + warp_n * 64 + na * 8 + c2;
                    float v0 = acc[ma][na][rr * 2], v1 = acc[ma][na][rr * 2 + 1];
                    __nv_bfloat16 h0, l0_, h1, l1_;
                    split2(v0, h0, l0_);
                    split2(v1, h1, l1_);
                    size_t g = (size_t)gm * HW + gn;
                    *(u32*)(Chi + g) = pack_bf(h0, h1);
                    *(u32*)(Clo + g) = pack_bf(l0_, l1_);
                }
            }
}

// ---------------- softmax + split alpha ----------------
__global__ void k_softmax() {
    const int warp = (blockIdx.x * blockDim.x + threadIdx.x) >> 5;
    const int lane = threadIdx.x & 31;
    if (warp >= 2 * BS * D) return;
    const float* row = g_scores + (size_t)warp * D;
    __nv_bfloat16* oh = g_al_hi + (size_t)warp * D;
    __nv_bfloat16* ol = g_al_lo + (size_t)warp * D;

    float m = -1e30f;
    for (int i = lane; i < D; i += 32) m = fmaxf(m, row[i]);
#pragma unroll
    for (int off = 16; off > 0; off >>= 1) m = fmaxf(m, __shfl_xor_sync(0xffffffffu, m, off));
    float s = 0.f;
    float e[14];
#pragma unroll
    for (int j = 0; j < 14; j++) { e[j] = __expf(row[lane + 32 * j] - m); s += e[j]; }
#pragma unroll
    for (int off = 16; off > 0; off >>= 1) s += __shfl_xor_sync(0xffffffffu, s, off);
    float inv = 1.0f / s;
#pragma unroll
    for (int j = 0; j < 14; j++) {
        __nv_bfloat16 h, l;
        split2(e[j] * inv, h, l);
        oh[lane + 32 * j] = h;
        ol[lane + 32 * j] = l;
    }
}

// =========================================================================
// k_out: M=128(d) N=64(h) K=448. Dual A (pos/neg) sharing trans-B tiles.
// (unchanged from the round-6 best)
// =========================================================================
#define OUT_P_H 0
#define OUT_P_L 10240
#define OUT_N_H 20480
#define OUT_N_L 30720
#define OUT_BH 40960
#define OUT_BL 45568
#define OUT_SMEM 50176

__global__ __launch_bounds__(256) void k_out(const float* __restrict__ Vs,
                                             float* __restrict__ out) {
    extern __shared__ char sm[];
    const u32 sb = smem_u32(sm);
    const int t = threadIdx.x, wid = t >> 5, l = t & 31;
    const int warp_m = wid & 3, warp_n = wid >> 2;

    const int b = blockIdx.z;
    const __nv_bfloat16* A1h = g_al_hi + (size_t)b * D * D;
    const __nv_bfloat16* A1l = g_al_lo + (size_t)b * D * D;
    const __nv_bfloat16* A2h = g_al_hi + (size_t)(BS + b) * D * D;
    const __nv_bfloat16* A2l = g_al_lo + (size_t)(BS + b) * D * D;
    const __nv_bfloat16* Bhi = g_V2_hi + (size_t)b * D * HW;
    const __nv_bfloat16* Blo = g_V2_lo + (size_t)b * D * HW;

    const int m0 = blockIdx.y * 128, n0 = blockIdx.x * 64;

    const u32 aRow = warp_m * 32 + (l & 15);
    const u32 aCol = (l >> 4) * 16;
    const u32 btRow = (l & 15);
    const u32 btCol = (l >> 4) * 16;

    float accP[2][4][4] = {};
    float accN[2][4][4] = {};

    for (int k0 = 0; k0 < D; k0 += 32) {
#pragma unroll
        for (int i = 0; i < 2; i++) {
            int idx = t + 256 * i;
            int m = idx & 127, c = idx >> 7;
            int gm = m0 + m; if (gm > 447) gm = 447;
            const size_t g = (size_t)gm * D + k0 + c * 8;
            *(uint4*)(sm + OUT_P_H + m * PA + c * 16) = *(const uint4*)(A1h + g);
            *(uint4*)(sm + OUT_P_L + m * PA + c * 16) = *(const uint4*)(A1l + g);
            *(uint4*)(sm + OUT_N_H + m * PA + c * 16) = *(const uint4*)(A2h + g);
            *(uint4*)(sm + OUT_N_L + m * PA + c * 16) = *(const uint4*)(A2l + g);
        }
        {
            int r = t >> 3, c = t & 7;
            const size_t g = (size_t)(k0 + r) * HW + n0 + c * 8;
            *(uint4*)(sm + OUT_BH + r * PBT + c * 16) = *(const uint4*)(Bhi + g);
            *(uint4*)(sm + OUT_BL + r * PBT + c * 16) = *(const uint4*)(Blo + g);
        }
        __syncthreads();
#pragma unroll
        for (int k16 = 0; k16 < 2; k16++) {
            u32 bh[8], bl[8];
#pragma unroll
            for (int p = 0; p < 2; p++) {
                u32 off = (k16 * 16 + btRow) * PBT + (warp_n * 32 + p * 16) * 2 + btCol;
                LDSM4T(bh[p * 4 + 0], bh[p * 4 + 1], bh[p * 4 + 2], bh[p * 4 + 3], sb + OUT_BH + off);
                LDSM4T(bl[p * 4 + 0], bl[p * 4 + 1], bl[p * 4 + 2], bl[p * 4 + 3], sb + OUT_BL + off);
            }
#pragma unroll
            for (int ma = 0; ma < 2; ma++) {
                u32 off = (aRow + ma * 16) * PA + aCol + k16 * 32;
                u32 ph[4], pl[4], nh[4], nl[4];
                LDSM4(ph[0], ph[1], ph[2], ph[3], sb + OUT_P_H + off);
                LDSM4(pl[0], pl[1], pl[2], pl[3], sb + OUT_P_L + off);
                LDSM4(nh[0], nh[1], nh[2], nh[3], sb + OUT_N_H + off);
                LDSM4(nl[0], nl[1], nl[2], nl[3], sb + OUT_N_L + off);
#pragma unroll
                for (int na = 0; na < 4; na++) {
                    u32 h0 = bh[na * 2], h1 = bh[na * 2 + 1];
                    u32 l0 = bl[na * 2], l1 = bl[na * 2 + 1];
                    float* dp = accP[ma][na];
                    float* dn = accN[ma][na];
                    MMA(dp, ph[0], ph[1], ph[2], ph[3], h0, h1);
                    MMA(dp, ph[0], ph[1], ph[2], ph[3], l0, l1);
                    MMA(dp, pl[0], pl[1], pl[2], pl[3], h0, h1);
                    MMA(dn, nh[0], nh[1], nh[2], nh[3], h0, h1);
                    MMA(dn, nh[0], nh[1], nh[2], nh[3], l0, l1);
                    MMA(dn, nl[0], nl[1], nl[2], nl[3], h0, h1);
                }
            }
        }
        __syncthreads();
    }

    float lsum = 0.f;
    const int r = l >> 2, c2 = (l & 3) * 2;
#pragma unroll
    for (int ma = 0; ma < 2; ma++)
#pragma unroll
        for (int na = 0; na < 4; na++)
#pragma unroll
            for (int rr = 0; rr < 2; rr++) {
                int gm = m0 + warp_m * 32 + ma * 16 + rr * 8 + r;
                if (gm < 448) {
                    int gn = n0 + warp_n * 32 + na * 8 + c2;
                    float p0 = accP[ma][na][rr * 2], p1 = accP[ma][na][rr * 2 + 1];
                    float q0 = accN[ma][na][rr * 2], q1 = accN[ma][na][rr * 2 + 1];
                    size_t g = ((size_t)b * D + gm) * HW + gn;
                    float2 vs = *(const float2*)(Vs + g);
                    *(float2*)(out + g) = make_float2(vs.x + p0, vs.y + p1);
                    lsum += fmaxf(q0 - p0 + 12.0f, 0.0f);
                    lsum += fmaxf(q1 - p1 + 12.0f, 0.0f);
                }
            }

    __syncthreads();
    float* red = (float*)sm;
    red[t] = lsum;
    __syncthreads();
#pragma unroll
    for (int s = 128; s > 0; s >>= 1) {
        if (t < s) red[t] += red[t + s];
        __syncthreads();
    }
    if (t == 0) atomicAdd(&g_Lsum, (double)red[0]);
}

__global__ void k_final(float* out, int out_size) {
    if (out_size > NELEM)
        out[NELEM] = (float)(g_Lsum / (double)NELEM);
}

extern "C" void kernel_launch(void* const* d_in, const int* in_sizes, int n_in,
                              void* d_out, int out_size) {
    const float* Vr = (const float*)d_in[0];
    const float* Vs = (const float*)d_in[1];
    const float* Wq = (const float*)d_in[2];
    const float* Wk = (const float*)d_in[3];
    const float* Wv = (const float*)d_in[4];
    float* out = (float*)d_out;

    cudaFuncSetAttribute(k_proj, cudaFuncAttributeMaxDynamicSharedMemorySize, PRJ_SMEM);
    cudaFuncSetAttribute(k_scores, cudaFuncAttributeMaxDynamicSharedMemorySize, SCR_SMEM);
    cudaFuncSetAttribute(k_out, cudaFuncAttributeMaxDynamicSharedMemorySize, OUT_SMEM);

    k_zero<<<1, 1>>>();
    k_split_v<<<14336, 256>>>(Vr, Vs);
    k_split_w<<<(3 * D * D + 255) / 256, 256>>>(Wq, Wk, Wv);
    k_proj<<<dim3(HW / 128, 4, BS * 3), 256, PRJ_SMEM>>>();
    k_scores<<<dim3(D / 64, 4, BS), 256, SCR_SMEM>>>();
    k_softmax<<<(2 * BS * D * 32 + 255) / 256, 256>>>();
    k_out<<<dim3(HW / 64, 4, BS), 256, OUT_SMEM>>>(Vs, out);
    k_final<<<1, 1>>>(out, out_size);
}